// round 6
// baseline (speedup 1.0000x reference)
#include <cuda_runtime.h>
#include <cuda_bf16.h>
#include <math.h>
#include <cstdint>

#define D 128
#define MAXN 50000
#define MAXE 800000

__device__ float g_support[MAXN * D];
__device__ unsigned g_hsup[MAXN * (D / 2)];   // support in bf16, packed pairs [m][k]
__device__ int   g_cnt[MAXN];
__device__ int   g_offs[MAXN];                // after scatter: END offset per row
__device__ int2  g_edge[MAXE];                // (col, val bits), binned by dest row
__device__ unsigned g_wt[D * (D / 2)];        // W^T bf16 packed pairs, [n][k]

// ---------------- CSR build ----------------

__global__ void zero_cnt_kernel(int n) {
    int i = blockIdx.x * blockDim.x + threadIdx.x;
    if (i < n) g_cnt[i] = 0;
}

__global__ void hist_kernel(const int* __restrict__ row, int E) {
    int e = blockIdx.x * blockDim.x + threadIdx.x;
    if (e < E) atomicAdd(&g_cnt[row[e]], 1);
}

// Single-block exclusive scan over n counters
__global__ void scan_all_kernel(int n) {
    __shared__ int part[1024];
    int t = threadIdx.x;
    int chunk = (n + 1023) >> 10;
    int base = t * chunk;
    int sum = 0;
    for (int j = 0; j < chunk; j++) {
        int i = base + j;
        if (i < n) sum += g_cnt[i];
    }
    part[t] = sum;
    __syncthreads();
    int v = sum;
    for (int d = 1; d < 1024; d <<= 1) {
        int tv = (t >= d) ? part[t - d] : 0;
        __syncthreads();
        part[t] += tv;
        __syncthreads();
    }
    int run = part[t] - v;  // exclusive prefix of this thread's chunk
    for (int j = 0; j < chunk; j++) {
        int i = base + j;
        if (i < n) { g_offs[i] = run; run += g_cnt[i]; }
    }
}

__global__ void scatter_kernel(const int* __restrict__ row, const int* __restrict__ col,
                               const float* __restrict__ vals, int E) {
    int e = blockIdx.x * blockDim.x + threadIdx.x;
    if (e < E) {
        int pos = atomicAdd(&g_offs[row[e]], 1);  // offs becomes END after this kernel
        g_edge[pos] = make_int2(col[e], __float_as_int(vals[e]));
    }
}

// ---------------- gather SpMM: support = (1-alpha)*A*input + alpha*h0 ----------------
// One warp per destination row. Writes fp32 support AND packed-bf16 copy.

__device__ __forceinline__ unsigned pack_bf16(float a, float b) {
    unsigned lo = (unsigned)__bfloat16_as_ushort(__float2bfloat16(a));
    unsigned hi = (unsigned)__bfloat16_as_ushort(__float2bfloat16(b));
    return lo | (hi << 16);
}

__global__ void gather_kernel(const float* __restrict__ input,
                              const float* __restrict__ h0,
                              const float* __restrict__ alpha_p, int N) {
    int wid  = (blockIdx.x * blockDim.x + threadIdx.x) >> 5;
    int lane = threadIdx.x & 31;
    if (wid >= N) return;
    int end = g_offs[wid];
    int beg = end - g_cnt[wid];
    const float4* in4 = (const float4*)input;

    float ax = 0.f, ay = 0.f, az = 0.f, aw = 0.f;
    int j = beg;
    for (; j + 8 <= end; j += 8) {
        int2 e[8];
#pragma unroll
        for (int q = 0; q < 8; q++) e[q] = __ldg(&g_edge[j + q]);
        float4 x[8];
#pragma unroll
        for (int q = 0; q < 8; q++) x[q] = __ldg(&in4[(size_t)e[q].x * 32 + lane]);
#pragma unroll
        for (int q = 0; q < 8; q++) {
            float v = __int_as_float(e[q].y);
            ax = fmaf(v, x[q].x, ax);
            ay = fmaf(v, x[q].y, ay);
            az = fmaf(v, x[q].z, az);
            aw = fmaf(v, x[q].w, aw);
        }
    }
    for (; j < end; j++) {
        int2 e = __ldg(&g_edge[j]);
        float v = __int_as_float(e.y);
        float4 x = __ldg(&in4[(size_t)e.x * 32 + lane]);
        ax = fmaf(v, x.x, ax);
        ay = fmaf(v, x.y, ay);
        az = fmaf(v, x.z, az);
        aw = fmaf(v, x.w, aw);
    }

    float a = *alpha_p, oma = 1.f - a;
    float4 h = ((const float4*)h0)[(size_t)wid * 32 + lane];
    float4 o = make_float4(fmaf(oma, ax, a * h.x),
                           fmaf(oma, ay, a * h.y),
                           fmaf(oma, az, a * h.z),
                           fmaf(oma, aw, a * h.w));
    ((float4*)g_support)[(size_t)wid * 32 + lane] = o;
    uint2 hb = make_uint2(pack_bf16(o.x, o.y), pack_bf16(o.z, o.w));
    ((uint2*)g_hsup)[(size_t)wid * 32 + lane] = hb;
}

// ---------------- W transpose + bf16: g_wt[n][k] = bf16(W[k][n]), packed pairs ----------------

__global__ void transpose_w_kernel(const float* __restrict__ W) {
    __shared__ float t[32][33];
    int n0 = blockIdx.x * 32, k0 = blockIdx.y * 32;
    t[threadIdx.y][threadIdx.x] = W[(k0 + threadIdx.y) * D + n0 + threadIdx.x];
    __syncthreads();
    // thread (x=kpair 0..15 handled by pairs) — simpler: 32x32 tile, each thread
    // with even x writes one packed pair (k = k0+x, k0+x+1)
    if ((threadIdx.x & 1) == 0) {
        float v0 = t[threadIdx.x][threadIdx.y];
        float v1 = t[threadIdx.x + 1][threadIdx.y];
        int n = n0 + threadIdx.y;
        int kp = (k0 + threadIdx.x) >> 1;
        g_wt[n * (D / 2) + kp] = pack_bf16(v0, v1);
    }
}

// ---------------- HMMA GEMM: out = theta*(S@W) + (1-theta)*S ----------------
// CTA: 256 threads (8 warps), 128 rows. Warp w: rows [w*16, w*16+16).
// mma.sync.m16n8k16 row.col bf16->f32. B (W^T) staged in smem with padded rows.

#define WT_PADU 34   // uints per padded W^T row (64 data + 2 pad -> stride 66? see below)

// We pad each W^T row (64 uints) to 66 uints so the per-n stride is 66 words
// (mod 32 = 2) -> the 8 n-groups of a B-fragment hit distinct banks.
#define SB_STRIDE 66

__global__ void __launch_bounds__(256) gemm_mma_kernel(
        const float* __restrict__ lamda_p,
        const int* __restrict__ l_p,
        float* __restrict__ out, int N) {
    __shared__ unsigned sB[D * SB_STRIDE];  // 128 rows * 66 uints = 33.8 KB

    int tid  = threadIdx.x;
    int lane = tid & 31;
    int w    = tid >> 5;
    int rowBase = blockIdx.x * 128 + w * 16;

    // stage W^T into padded smem
    for (int i = tid; i < D * (D / 2); i += 256) {
        int n = i >> 6;
        int q = i & 63;
        sB[n * SB_STRIDE + q] = g_wt[i];
    }
    __syncthreads();

    int r0 = lane >> 2;   // 0..7
    int tg = lane & 3;    // 0..3

    int rowA = rowBase + r0;
    int rowB = rowA + 8;
    int rA = min(rowA, N - 1);   // clamp; garbage rows discarded at store
    int rB = min(rowB, N - 1);

    float acc[16][4];
#pragma unroll
    for (int nt = 0; nt < 16; nt++)
#pragma unroll
        for (int q = 0; q < 4; q++) acc[nt][q] = 0.f;

    const unsigned* gA = g_hsup;

#pragma unroll
    for (int k = 0; k < 8; k++) {   // k-step of 16: pair-index base k*8
        unsigned a0 = __ldg(&gA[(size_t)rA * 64 + k * 8 + tg]);
        unsigned a1 = __ldg(&gA[(size_t)rB * 64 + k * 8 + tg]);
        unsigned a2 = __ldg(&gA[(size_t)rA * 64 + k * 8 + 4 + tg]);
        unsigned a3 = __ldg(&gA[(size_t)rB * 64 + k * 8 + 4 + tg]);
#pragma unroll
        for (int nt = 0; nt < 16; nt++) {
            int n = nt * 8 + r0;
            unsigned b0 = sB[n * SB_STRIDE + k * 8 + tg];
            unsigned b1 = sB[n * SB_STRIDE + k * 8 + 4 + tg];
            asm volatile(
                "mma.sync.aligned.m16n8k16.row.col.f32.bf16.bf16.f32 "
                "{%0,%1,%2,%3}, {%4,%5,%6,%7}, {%8,%9}, {%0,%1,%2,%3};"
                : "+f"(acc[nt][0]), "+f"(acc[nt][1]), "+f"(acc[nt][2]), "+f"(acc[nt][3])
                : "r"(a0), "r"(a1), "r"(a2), "r"(a3), "r"(b0), "r"(b1));
        }
    }

    float theta = logf(*lamda_p / (float)(*l_p) + 1.0f);
    float om = 1.0f - theta;

#pragma unroll
    for (int nt = 0; nt < 16; nt++) {
        int c = nt * 8 + tg * 2;
        if (rowA < N) {
            float2 s = *(const float2*)&g_support[(size_t)rowA * D + c];
            float2 o;
            o.x = fmaf(theta, acc[nt][0], om * s.x);
            o.y = fmaf(theta, acc[nt][1], om * s.y);
            *(float2*)&out[(size_t)rowA * D + c] = o;
        }
        if (rowB < N) {
            float2 s = *(const float2*)&g_support[(size_t)rowB * D + c];
            float2 o;
            o.x = fmaf(theta, acc[nt][2], om * s.x);
            o.y = fmaf(theta, acc[nt][3], om * s.y);
            *(float2*)&out[(size_t)rowB * D + c] = o;
        }
    }
}

// ---------------- launch ----------------

extern "C" void kernel_launch(void* const* d_in, const int* in_sizes, int n_in,
                              void* d_out, int out_size) {
    const float* input  = (const float*)d_in[0];
    const float* h0     = (const float*)d_in[1];
    const float* vals   = (const float*)d_in[2];
    const float* W      = (const float*)d_in[3];
    const float* lamda  = (const float*)d_in[4];
    const float* alpha  = (const float*)d_in[5];
    const int*   row    = (const int*)d_in[6];
    const int*   col    = (const int*)d_in[7];
    const int*   l      = (const int*)d_in[8];
    float* out = (float*)d_out;

    int N = in_sizes[0] / D;
    int E = in_sizes[2];

    zero_cnt_kernel<<<(N + 255) / 256, 256>>>(N);
    hist_kernel<<<(E + 255) / 256, 256>>>(row, E);
    scan_all_kernel<<<1, 1024>>>(N);
    scatter_kernel<<<(E + 255) / 256, 256>>>(row, col, vals, E);

    gather_kernel<<<(N * 32 + 255) / 256, 256>>>(input, h0, alpha, N);

    transpose_w_kernel<<<dim3(4, 4), dim3(32, 32)>>>(W);

    gemm_mma_kernel<<<(N + 127) / 128, 256>>>(lamda, l, out, N);
}

// round 7
// speedup vs baseline: 1.4741x; 1.4741x over previous
#include <cuda_runtime.h>
#include <cuda_bf16.h>
#include <cuda_fp16.h>
#include <math.h>
#include <cstdint>

#define D 128
#define MAXN 50000
#define MAXE 800000

__device__ float g_support[MAXN * D];
__device__ unsigned g_hsup[MAXN * (D / 2)];   // support in bf16 packed pairs [m][k]
__device__ uint2 g_hin[MAXN * 32];            // input in fp16: 32 uint2 (128 halves) per row
__device__ int   g_cnt[MAXN];
__device__ int   g_offs[MAXN];                // scan1: local-excl; after scatter: local END
__device__ int   g_bsums[64];                 // superblock bases
__device__ int2  g_edge[MAXE];                // (col, val bits), binned by dest row
__device__ unsigned g_wt[D * (D / 2)];        // W^T bf16 packed pairs, [n][k]

__device__ __forceinline__ unsigned pack_bf16(float a, float b) {
    unsigned lo = (unsigned)__bfloat16_as_ushort(__float2bfloat16(a));
    unsigned hi = (unsigned)__bfloat16_as_ushort(__float2bfloat16(b));
    return lo | (hi << 16);
}

// ---------------- CSR build ----------------

__global__ void zero_cnt_kernel(int n) {
    int i = blockIdx.x * blockDim.x + threadIdx.x;
    if (i < n) g_cnt[i] = 0;
}

__global__ void hist_kernel(const int* __restrict__ row, int E) {
    int e = blockIdx.x * blockDim.x + threadIdx.x;
    if (e < E) atomicAdd(&g_cnt[row[e]], 1);
}

__global__ void scan1_kernel(int n) {
    __shared__ int s[1024];
    int i = blockIdx.x * 1024 + threadIdx.x;
    int v = (i < n) ? g_cnt[i] : 0;
    s[threadIdx.x] = v;
    __syncthreads();
    for (int d = 1; d < 1024; d <<= 1) {
        int t = (threadIdx.x >= d) ? s[threadIdx.x - d] : 0;
        __syncthreads();
        s[threadIdx.x] += t;
        __syncthreads();
    }
    if (i < n) g_offs[i] = s[threadIdx.x] - v;  // exclusive within superblock
    if (threadIdx.x == 1023) g_bsums[blockIdx.x] = s[1023];
}

__global__ void scan2_kernel(int nb) {
    __shared__ int s[64];
    int i = threadIdx.x;
    int v = (i < nb) ? g_bsums[i] : 0;
    s[i] = v;
    __syncthreads();
    for (int d = 1; d < 64; d <<= 1) {
        int t = (i >= d) ? s[i - d] : 0;
        __syncthreads();
        s[i] += t;
        __syncthreads();
    }
    if (i < nb) g_bsums[i] = s[i] - v;
}

__global__ void scatter_kernel(const int* __restrict__ row, const int* __restrict__ col,
                               const float* __restrict__ vals, int E) {
    int e = blockIdx.x * blockDim.x + threadIdx.x;
    if (e < E) {
        int r = row[e];
        int pos = g_bsums[r >> 10] + atomicAdd(&g_offs[r], 1);
        g_edge[pos] = make_int2(col[e], __float_as_int(vals[e]));
    }
}

// ---------------- input -> fp16 ----------------

__global__ void convert_input_kernel(const float* __restrict__ input, int n4) {
    int i = blockIdx.x * blockDim.x + threadIdx.x;
    if (i >= n4) return;
    float4 v = ((const float4*)input)[i];
    __half2 a = __floats2half2_rn(v.x, v.y);
    __half2 b = __floats2half2_rn(v.z, v.w);
    g_hin[i] = make_uint2(*(unsigned*)&a, *(unsigned*)&b);
}

// ---------------- gather SpMM ----------------

__global__ void gather_kernel(const float* __restrict__ h0,
                              const float* __restrict__ alpha_p, int N) {
    int wid  = (blockIdx.x * blockDim.x + threadIdx.x) >> 5;
    int lane = threadIdx.x & 31;
    if (wid >= N) return;
    int endl = g_offs[wid];
    int end  = g_bsums[wid >> 10] + endl;
    int beg  = end - g_cnt[wid];

    float ax = 0.f, ay = 0.f, az = 0.f, aw = 0.f;
    int j = beg;
    for (; j + 8 <= end; j += 8) {
        int2 e[8];
#pragma unroll
        for (int q = 0; q < 8; q++) e[q] = __ldg(&g_edge[j + q]);
        uint2 x[8];
#pragma unroll
        for (int q = 0; q < 8; q++) x[q] = __ldg(&g_hin[(size_t)e[q].x * 32 + lane]);
#pragma unroll
        for (int q = 0; q < 8; q++) {
            float v = __int_as_float(e[q].y);
            __half2 p0 = *(__half2*)&x[q].x;
            __half2 p1 = *(__half2*)&x[q].y;
            float2 f0 = __half22float2(p0);
            float2 f1 = __half22float2(p1);
            ax = fmaf(v, f0.x, ax);
            ay = fmaf(v, f0.y, ay);
            az = fmaf(v, f1.x, az);
            aw = fmaf(v, f1.y, aw);
        }
    }
    for (; j < end; j++) {
        int2 e = __ldg(&g_edge[j]);
        float v = __int_as_float(e.y);
        uint2 x = __ldg(&g_hin[(size_t)e.x * 32 + lane]);
        __half2 p0 = *(__half2*)&x.x;
        __half2 p1 = *(__half2*)&x.y;
        float2 f0 = __half22float2(p0);
        float2 f1 = __half22float2(p1);
        ax = fmaf(v, f0.x, ax);
        ay = fmaf(v, f0.y, ay);
        az = fmaf(v, f1.x, az);
        aw = fmaf(v, f1.y, aw);
    }

    float a = *alpha_p, oma = 1.f - a;
    float4 h = ((const float4*)h0)[(size_t)wid * 32 + lane];
    float4 o = make_float4(fmaf(oma, ax, a * h.x),
                           fmaf(oma, ay, a * h.y),
                           fmaf(oma, az, a * h.z),
                           fmaf(oma, aw, a * h.w));
    ((float4*)g_support)[(size_t)wid * 32 + lane] = o;
    uint2 hb = make_uint2(pack_bf16(o.x, o.y), pack_bf16(o.z, o.w));
    ((uint2*)g_hsup)[(size_t)wid * 32 + lane] = hb;
}

// ---------------- W transpose + bf16 ----------------

__global__ void transpose_w_kernel(const float* __restrict__ W) {
    __shared__ float t[32][33];
    int n0 = blockIdx.x * 32, k0 = blockIdx.y * 32;
    t[threadIdx.y][threadIdx.x] = W[(k0 + threadIdx.y) * D + n0 + threadIdx.x];
    __syncthreads();
    if ((threadIdx.x & 1) == 0) {
        float v0 = t[threadIdx.x][threadIdx.y];
        float v1 = t[threadIdx.x + 1][threadIdx.y];
        int n = n0 + threadIdx.y;
        int kp = (k0 + threadIdx.x) >> 1;
        g_wt[n * (D / 2) + kp] = pack_bf16(v0, v1);
    }
}

// ---------------- HMMA GEMM ----------------

#define SB_STRIDE 66

__global__ void __launch_bounds__(256) gemm_mma_kernel(
        const float* __restrict__ lamda_p,
        const int* __restrict__ l_p,
        float* __restrict__ out, int N) {
    __shared__ unsigned sB[D * SB_STRIDE];

    int tid  = threadIdx.x;
    int lane = tid & 31;
    int w    = tid >> 5;
    int rowBase = blockIdx.x * 128 + w * 16;

    for (int i = tid; i < D * (D / 2); i += 256) {
        int n = i >> 6;
        int q = i & 63;
        sB[n * SB_STRIDE + q] = g_wt[i];
    }
    __syncthreads();

    int r0 = lane >> 2;
    int tg = lane & 3;

    int rowA = rowBase + r0;
    int rowB = rowA + 8;
    int rA = min(rowA, N - 1);
    int rB = min(rowB, N - 1);

    float acc[16][4];
#pragma unroll
    for (int nt = 0; nt < 16; nt++)
#pragma unroll
        for (int q = 0; q < 4; q++) acc[nt][q] = 0.f;

    const unsigned* gA = g_hsup;

#pragma unroll
    for (int k = 0; k < 8; k++) {
        unsigned a0 = __ldg(&gA[(size_t)rA * 64 + k * 8 + tg]);
        unsigned a1 = __ldg(&gA[(size_t)rB * 64 + k * 8 + tg]);
        unsigned a2 = __ldg(&gA[(size_t)rA * 64 + k * 8 + 4 + tg]);
        unsigned a3 = __ldg(&gA[(size_t)rB * 64 + k * 8 + 4 + tg]);
#pragma unroll
        for (int nt = 0; nt < 16; nt++) {
            int n = nt * 8 + r0;
            unsigned b0 = sB[n * SB_STRIDE + k * 8 + tg];
            unsigned b1 = sB[n * SB_STRIDE + k * 8 + 4 + tg];
            asm volatile(
                "mma.sync.aligned.m16n8k16.row.col.f32.bf16.bf16.f32 "
                "{%0,%1,%2,%3}, {%4,%5,%6,%7}, {%8,%9}, {%0,%1,%2,%3};"
                : "+f"(acc[nt][0]), "+f"(acc[nt][1]), "+f"(acc[nt][2]), "+f"(acc[nt][3])
                : "r"(a0), "r"(a1), "r"(a2), "r"(a3), "r"(b0), "r"(b1));
        }
    }

    float theta = logf(*lamda_p / (float)(*l_p) + 1.0f);
    float om = 1.0f - theta;

#pragma unroll
    for (int nt = 0; nt < 16; nt++) {
        int c = nt * 8 + tg * 2;
        if (rowA < N) {
            float2 s = *(const float2*)&g_support[(size_t)rowA * D + c];
            float2 o;
            o.x = fmaf(theta, acc[nt][0], om * s.x);
            o.y = fmaf(theta, acc[nt][1], om * s.y);
            *(float2*)&out[(size_t)rowA * D + c] = o;
        }
        if (rowB < N) {
            float2 s = *(const float2*)&g_support[(size_t)rowB * D + c];
            float2 o;
            o.x = fmaf(theta, acc[nt][2], om * s.x);
            o.y = fmaf(theta, acc[nt][3], om * s.y);
            *(float2*)&out[(size_t)rowB * D + c] = o;
        }
    }
}

// ---------------- launch ----------------

extern "C" void kernel_launch(void* const* d_in, const int* in_sizes, int n_in,
                              void* d_out, int out_size) {
    const float* input  = (const float*)d_in[0];
    const float* h0     = (const float*)d_in[1];
    const float* vals   = (const float*)d_in[2];
    const float* W      = (const float*)d_in[3];
    const float* lamda  = (const float*)d_in[4];
    const float* alpha  = (const float*)d_in[5];
    const int*   row    = (const int*)d_in[6];
    const int*   col    = (const int*)d_in[7];
    const int*   l      = (const int*)d_in[8];
    float* out = (float*)d_out;

    int N = in_sizes[0] / D;
    int E = in_sizes[2];

    zero_cnt_kernel<<<(N + 255) / 256, 256>>>(N);
    hist_kernel<<<(E + 255) / 256, 256>>>(row, E);
    int nScanBlocks = (N + 1023) / 1024;
    scan1_kernel<<<nScanBlocks, 1024>>>(N);
    scan2_kernel<<<1, 64>>>(nScanBlocks);
    scatter_kernel<<<(E + 255) / 256, 256>>>(row, col, vals, E);

    convert_input_kernel<<<(N * 32 + 255) / 256, 256>>>(input, N * 32);

    gather_kernel<<<(N * 32 + 255) / 256, 256>>>(h0, alpha, N);

    transpose_w_kernel<<<dim3(4, 4), dim3(32, 32)>>>(W);

    gemm_mma_kernel<<<(N + 127) / 128, 256>>>(lamda, l, out, N);
}